// round 17
// baseline (speedup 1.0000x reference)
#include <cuda_runtime.h>
#include <cuda_fp16.h>
#include <cstdint>

#define THREADS 256
#define TILE_B  64

// ---------------- smem byte map (per CTA, 4 CTAs/SM) ----------------
#define OFF_XS  0          // Xs hi [64][64] f16, swizzled        8192
#define OFF_H   8192       // H hi [64][256] f16; then GEMM2 partials (16KB)
#define OFF_ES  40960      // escl 64 f32                          256
#define OFF_B1  41216      // b1 as half2 [128]                    512
#define OFF_B2  41728      // b2   64 f32                          256
#define SMEM_BYTES 41984

#define U4(row, p, c2) ((((row) * (c2)) + ((p) ^ (((row) & 7) << 2))) << 2)

// W in mma B-FRAGMENT order; 64 slots/half x 32 lanes = 2048 uint4 per half.
__device__ __align__(16) unsigned char g_Wbuf[65536];

__device__ __forceinline__ float ex2f(float v) {
    float y; asm("ex2.approx.f32 %0, %1;" : "=f"(y) : "f"(v)); return y;
}
__device__ __forceinline__ float lg2f(float v) {
    float y; asm("lg2.approx.f32 %0, %1;" : "=f"(y) : "f"(v)); return y;
}
__device__ __forceinline__ uint32_t packh(float lo, float hi) {
    half2 h = __floats2half2_rn(lo, hi);
    return *(uint32_t*)&h;
}
__device__ __forceinline__ void mma16816(float* c, const uint32_t* a, uint32_t b0, uint32_t b1) {
    asm volatile(
        "mma.sync.aligned.m16n8k16.row.col.f32.f16.f16.f32 "
        "{%0,%1,%2,%3}, {%4,%5,%6,%7}, {%8,%9}, {%0,%1,%2,%3};"
        : "+f"(c[0]), "+f"(c[1]), "+f"(c[2]), "+f"(c[3])
        : "r"(a[0]), "r"(a[1]), "r"(a[2]), "r"(a[3]), "r"(b0), "r"(b1));
}
__device__ __forceinline__ void ldm_x4(uint32_t* d, uint32_t addr) {
    asm volatile("ldmatrix.sync.aligned.m8n8.x4.shared.b16 {%0,%1,%2,%3}, [%4];"
        : "=r"(d[0]), "=r"(d[1]), "=r"(d[2]), "=r"(d[3]) : "r"(addr));
}

// ---------------- prep kernel: W fp32 -> fp16 B-fragments (2048 threads!) ----
__global__ void prep_w_kernel(const float* __restrict__ W1, const float* __restrict__ W2) {
    int idx = blockIdx.x * 256 + threadIdx.x;
    int lane = idx & 31, g = lane >> 2, tg = lane & 3;
    {   // W1 [256 n][64 k] -> frag slots (nw,kb,jj)
        int jj = (idx >> 5) & 3, kb = (idx >> 7) & 3, nw = (idx >> 9) & 3;
        int n = nw * 64 + jj * 16 + g;
        int k = kb * 16 + 2 * tg;
        uint4 v;
        v.x = packh(W1[n * 64 + k],           W1[n * 64 + k + 1]);
        v.y = packh(W1[n * 64 + k + 8],       W1[n * 64 + k + 9]);
        v.z = packh(W1[(n + 8) * 64 + k],     W1[(n + 8) * 64 + k + 1]);
        v.w = packh(W1[(n + 8) * 64 + k + 8], W1[(n + 8) * 64 + k + 9]);
        ((uint4*)g_Wbuf)[idx] = v;
    }
    {   // W2 [64 n][256 k] -> frag slots (nw,kb)
        int kb = (idx >> 5) & 15, nw = (idx >> 9) & 3;
        int n = nw * 16 + g;
        int k = kb * 16 + 2 * tg;
        uint4 v;
        v.x = packh(W2[n * 256 + k],           W2[n * 256 + k + 1]);
        v.y = packh(W2[n * 256 + k + 8],       W2[n * 256 + k + 9]);
        v.z = packh(W2[(n + 8) * 256 + k],     W2[(n + 8) * 256 + k + 1]);
        v.w = packh(W2[(n + 8) * 256 + k + 8], W2[(n + 8) * 256 + k + 9]);
        ((uint4*)(g_Wbuf + 32768))[idx] = v;
    }
}

__global__ __launch_bounds__(THREADS, 4)
void aniso_mma_kernel(const float* __restrict__ x, const float* __restrict__ r,
                      const float* __restrict__ b1, const float* __restrict__ b2,
                      float* __restrict__ out, int B)
{
    extern __shared__ char sm[];
    uint32_t smb;
    asm("{ .reg .u64 t; cvta.to.shared.u64 t, %1; cvt.u32.u64 %0, t; }" : "=r"(smb) : "l"(sm));
    float*  esclp = (float*)(sm + OFF_ES);
    __half2* b1h2 = (__half2*)(sm + OFF_B1);
    float*  b2s   = (float*)(sm + OFF_B2);

    const int tid  = threadIdx.x;
    const int lane = tid & 31;
    const int wid  = tid >> 5;
    const long long gb = (long long)blockIdx.x * TILE_B;

    if (tid < 128) b1h2[tid] = __floats2half2_rn(b1[2 * tid], b1[2 * tid + 1]);
    if (tid < 64)  b2s[tid] = b2[tid];

    // ---- log-domain Newton: 4-lane group per sample, coalesced x loads ----
    // lane tg owns cols {16*q4 + 4*tg + e}: per LDG.128 the 4 tg lanes cover a
    // contiguous 64B chunk per row -> 8 lines/instr (was 16).
    {
        const float L2E = 1.4426950408889634f;
        const int sg = lane >> 2;
        const int cb = (lane & 3) << 2;           // 4*tg
        const int m  = wid * 8 + sg;              // 0..63
        long long row = gb + m; if (row >= B) row = B - 1;

        float X[16], R[16];
        #pragma unroll
        for (int q4 = 0; q4 < 4; ++q4) {
            float4 v = *(const float4*)(x + row * 64 + q4 * 16 + cb);
            X[q4*4+0] = v.x; X[q4*4+1] = v.y; X[q4*4+2] = v.z; X[q4*4+3] = v.w;
            float4 rv = *(const float4*)(r + q4 * 16 + cb);
            R[q4*4+0] = rv.x; R[q4*4+1] = rv.y; R[q4*4+2] = rv.z; R[q4*4+3] = rv.w;
        }

        float s = 0.0f;
        bool conv = false;
        for (int it = 0; it < 30; ++it) {
            if (__all_sync(0xffffffffu, conv)) break;
            float c = (-2.0f * L2E) * s;
            float v = 0.0f, d = 0.0f;
            #pragma unroll
            for (int j = 0; j < 16; ++j) {
                float t = ex2f(R[j] * c) * (X[j] * X[j]);
                v += t; d += R[j] * t;
            }
            v += __shfl_xor_sync(0xffffffffu, v, 1);
            d += __shfl_xor_sync(0xffffffffu, d, 1);
            v += __shfl_xor_sync(0xffffffffu, v, 2);
            d += __shfl_xor_sync(0xffffffffu, d, 2);
            if (v < 1e-20f) conv = true;
            else if (fabsf(v - 1.0f) < 1e-6f) conv = true;
            float den = (2.0f * L2E) * d;
            den = (den == 0.0f) ? 1.0f : den;
            if (!conv) s += v * __fdividef(lg2f(v), den);
        }

        float cH = -L2E * s;
        #pragma unroll
        for (int j = 0; j < 16; j += 2) {
            float xs0 = X[j]     * ex2f(R[j]     * cH);
            float xs1 = X[j + 1] * ex2f(R[j + 1] * cH);
            int col = ((j >> 2) << 4) + cb + (j & 3);   // even, pairs adjacent
            *(uint32_t*)(sm + OFF_XS + U4(m, col >> 1, 32)) = packh(xs0, xs1);
        }
        if ((lane & 3) == 0) esclp[m] = ex2f(L2E * s);
    }
    __syncthreads();

    const int g  = lane >> 2;
    const int tg = lane & 3;
    const int mw = wid & 1;      // 2 M tiles of 32
    const int nw = wid >> 1;     // GEMM1: 4 N tiles
    const int os = (wid >> 1) & 1;  // GEMM2: o-half
    const int ks = wid >> 2;        // GEMM2: k-half

    const int lr  = lane & 7, seg = lane >> 3;
    const int arow = mw * 32 + lr + ((seg & 1) << 3);
    const int apo  = (seg & 2) << 1;
    const int axor = (arow & 7) << 2;

    const uint4* Wf1 = (const uint4*)g_Wbuf;
    const uint4* Wf2 = (const uint4*)(g_Wbuf + 32768);
    const __half2 z2 = __floats2half2_rn(0.0f, 0.0f);

    // ---- GEMM1: [64x256] = Xh[64x64] @ W1h^T, 2 N-passes, warp tile 32x32 ----
    #pragma unroll
    for (int npass = 0; npass < 2; ++npass) {
        const int c32 = npass * 4 + nw;
        const int slotbase = (c32 >> 1) * 16 + (c32 & 1) * 2;

        float acc[2][4][4];
        #pragma unroll
        for (int mi = 0; mi < 2; ++mi)
            #pragma unroll
            for (int j = 0; j < 4; ++j)
                #pragma unroll
                for (int q = 0; q < 4; ++q) acc[mi][j][q] = 0.0f;

        const uint32_t aB = smb + OFF_XS + arow * 128;
        #pragma unroll
        for (int kb = 0; kb < 4; ++kb) {
            uint32_t a0[4], a1[4];
            int kb2 = kb * 8;
            ldm_x4(a0, aB +        (((kb2 + apo) ^ axor) << 2));
            ldm_x4(a1, aB + 2048 + (((kb2 + apo) ^ axor) << 2));
            #pragma unroll
            for (int jj = 0; jj < 2; ++jj) {
                uint4 q = __ldg(Wf1 + ((slotbase + kb * 4 + jj) << 5) + lane);
                mma16816(acc[0][2*jj],     a0, q.x, q.y);
                mma16816(acc[1][2*jj],     a1, q.x, q.y);
                mma16816(acc[0][2*jj + 1], a0, q.z, q.w);
                mma16816(acc[1][2*jj + 1], a1, q.z, q.w);
            }
        }

        // epilogue (this pass): +b1, relu in half2 -> H (swizzled)
        #pragma unroll
        for (int mi = 0; mi < 2; ++mi) {
            int r0 = mw * 32 + mi * 16 + g;
            #pragma unroll
            for (int j = 0; j < 4; ++j) {
                int col = c32 * 32 + j * 8 + 2 * tg;
                int p = col >> 1;
                __half2 bb = b1h2[p];
                __half2 h0 = __hmax2(__hadd2(__floats2half2_rn(acc[mi][j][0], acc[mi][j][1]), bb), z2);
                __half2 h1 = __hmax2(__hadd2(__floats2half2_rn(acc[mi][j][2], acc[mi][j][3]), bb), z2);
                *(__half2*)(sm + OFF_H + U4(r0,     p, 128)) = h0;
                *(__half2*)(sm + OFF_H + U4(r0 + 8, p, 128)) = h1;
            }
        }
    }
    __syncthreads();

    // ---- GEMM2 split-K: warp (mw, os, ks) -> tile 32m x 32o, K = 128 ----
    float acc2[32];   // [mi][j][q] = acc2[mi*16 + j*4 + q]
    #pragma unroll
    for (int i = 0; i < 32; ++i) acc2[i] = 0.0f;

    {
        const uint32_t aB = smb + OFF_H + arow * 512;
        #pragma unroll
        for (int kb = 0; kb < 8; ++kb) {
            uint32_t a0[4], a1[4];
            int kbi = ks * 8 + kb;
            int kb2 = kbi * 8;
            ldm_x4(a0, aB +        (((kb2 + apo) ^ axor) << 2));
            ldm_x4(a1, aB + 8192 + (((kb2 + apo) ^ axor) << 2));
            #pragma unroll
            for (int j2 = 0; j2 < 2; ++j2) {
                uint4 q = __ldg(Wf2 + (((os * 2 + j2) * 16 + kbi) << 5) + lane);
                mma16816(&acc2[0*16 + (j2*2)*4],     a0, q.x, q.y);
                mma16816(&acc2[1*16 + (j2*2)*4],     a1, q.x, q.y);
                mma16816(&acc2[0*16 + (j2*2+1)*4],   a0, q.z, q.w);
                mma16816(&acc2[1*16 + (j2*2+1)*4],   a1, q.z, q.w);
            }
        }
    }
    __syncthreads();   // H dead -> reuse as partial buffer (4 x 4KB)

    float* part = (float*)(sm + OFF_H) + (mw * 2 + os) * 1024 + lane * 32;
    if (ks == 1) {
        #pragma unroll
        for (int i = 0; i < 8; ++i)
            ((float4*)part)[i] = make_float4(acc2[4*i], acc2[4*i+1], acc2[4*i+2], acc2[4*i+3]);
    }
    __syncthreads();

    if (ks == 0) {
        #pragma unroll
        for (int i = 0; i < 8; ++i) {
            float4 v = ((const float4*)part)[i];
            acc2[4*i]   += v.x; acc2[4*i+1] += v.y;
            acc2[4*i+2] += v.z; acc2[4*i+3] += v.w;
        }
        // epilogue2: +b2, * e^{s}, store
        #pragma unroll
        for (int mi = 0; mi < 2; ++mi) {
            int lr0 = mw * 32 + mi * 16 + g;
            int lr1 = lr0 + 8;
            float e0 = esclp[lr0], e1 = esclp[lr1];
            long long row0 = gb + lr0, row1 = gb + lr1;
            #pragma unroll
            for (int j = 0; j < 4; ++j) {
                int col = os * 32 + j * 8 + 2 * tg;
                float bb0 = b2s[col], bb1 = b2s[col + 1];
                float q0 = acc2[mi*16 + j*4 + 0], q1 = acc2[mi*16 + j*4 + 1];
                float q2 = acc2[mi*16 + j*4 + 2], q3 = acc2[mi*16 + j*4 + 3];
                if (row0 < B)
                    *(float2*)(out + row0 * 64 + col) =
                        make_float2((q0 + bb0) * e0, (q1 + bb1) * e0);
                if (row1 < B)
                    *(float2*)(out + row1 * 64 + col) =
                        make_float2((q2 + bb0) * e1, (q3 + bb1) * e1);
            }
        }
    }
}

extern "C" void kernel_launch(void* const* d_in, const int* in_sizes, int n_in,
                              void* d_out, int out_size) {
    const float* x  = (const float*)d_in[0];
    const float* r  = (const float*)d_in[1];
    const float* W1 = (const float*)d_in[2];
    const float* b1 = (const float*)d_in[3];
    const float* W2 = (const float*)d_in[4];
    const float* b2 = (const float*)d_in[5];
    float* out = (float*)d_out;

    const int B = in_sizes[0] / 64;
    const int grid = (B + TILE_B - 1) / TILE_B;

    prep_w_kernel<<<8, 256>>>(W1, W2);   // exactly 2048 threads = 2048 uint4 per half

    cudaFuncSetAttribute(aniso_mma_kernel,
                         cudaFuncAttributeMaxDynamicSharedMemorySize, SMEM_BYTES);
    aniso_mma_kernel<<<grid, THREADS, SMEM_BYTES>>>(x, r, b1, b2, out, B);
}